// round 8
// baseline (speedup 1.0000x reference)
#include <cuda_runtime.h>
#include <math.h>

#define NN 100000
#define HID 128
#define RR 8
#define LL 2
#define HH 4
#define DD 32
#define EE 625000
#define KB (NN * RR)            // 800000 sort buckets (dst*8 + rel)
#define NB2 782                 // ceil(KB/1024)

typedef unsigned long long ull;

// packed fp32x2 helpers (FFMA2 — only reachable via PTX fma.rn.f32x2)
__device__ __forceinline__ ull pack2(float x) {
    ull r;
    unsigned u = __float_as_uint(x);
    asm("mov.b64 %0, {%1, %1};" : "=l"(r) : "r"(u));
    return r;
}
#define FMA2(acc, a, b) asm("fma.rn.f32x2 %0, %1, %2, %0;" : "+l"(acc) : "l"(a), "l"(b))
__device__ __forceinline__ float2 unpack2(ull v) {
    unsigned lo, hi;
    asm("mov.b64 {%0, %1}, %2;" : "=r"(lo), "=r"(hi) : "l"(v));
    return make_float2(__uint_as_float(lo), __uint_as_float(hi));
}

// ---------------- scratch (device globals; no allocation) ----------------
__device__ float g_h[(size_t)NN * HID];
__device__ float g_kqv[(size_t)NN * 3 * HID];
__device__ float g_aggr[(size_t)NN * HID];
__device__ float g_Qt[(size_t)KB * HID];    // q~ per nonempty run (prescaled by pr*scale)
__device__ float g_Vr[(size_t)KB * HID];    // raw v-sum, then transformed in place
__device__ float g_rm[(size_t)KB * HH];     // per-run flash max
__device__ float g_rd[(size_t)KB * HH];     // per-run denom
__device__ int   g_deg[KB];
__device__ int   g_cur[KB];
__device__ int   g_off[KB + 1];
__device__ int   g_bsum[1024];
__device__ int   g_esrc[EE];
__device__ int   g_runidx[KB];              // bucket -> run index (r*NN+idx) or -1
__device__ int   g_lnode[KB];               // run index -> node
__device__ int   g_lcnt[RR];

// ---------------- gather ----------------
__global__ void gather_kernel(const float* __restrict__ emb, const int* __restrict__ x) {
    size_t i = (size_t)blockIdx.x * blockDim.x + threadIdx.x;
    if (i >= (size_t)NN * HID) return;
    int node = (int)(i >> 7);
    int c = (int)(i & 127);
    g_h[i] = emb[(size_t)x[node] * HID + c];
}

// ---------------- counting sort by (dst, rel) -> CSR ----------------
__global__ void zero_deg_kernel() {
    int i = blockIdx.x * blockDim.x + threadIdx.x;
    if (i < KB) g_deg[i] = 0;
    if (i < RR) g_lcnt[i] = 0;
}
__global__ void hist_kernel(const int* __restrict__ ei, const int* __restrict__ et) {
    int e = blockIdx.x * blockDim.x + threadIdx.x;
    if (e < EE) atomicAdd(&g_deg[ei[EE + e] * RR + et[e]], 1);
}
__global__ __launch_bounds__(1024) void scan1_kernel() {
    __shared__ int s[1024];
    int i = blockIdx.x * 1024 + threadIdx.x;
    int v = (i < KB) ? g_deg[i] : 0;
    s[threadIdx.x] = v;
    __syncthreads();
    for (int off = 1; off < 1024; off <<= 1) {
        int t = (threadIdx.x >= off) ? s[threadIdx.x - off] : 0;
        __syncthreads();
        s[threadIdx.x] += t;
        __syncthreads();
    }
    if (i < KB) g_off[i] = s[threadIdx.x] - v;
    if (threadIdx.x == 1023) g_bsum[blockIdx.x] = s[1023];
}
__global__ __launch_bounds__(1024) void scan2_kernel() {
    __shared__ int s[1024];
    int v = (threadIdx.x < NB2) ? g_bsum[threadIdx.x] : 0;
    s[threadIdx.x] = v;
    __syncthreads();
    for (int off = 1; off < 1024; off <<= 1) {
        int t = (threadIdx.x >= off) ? s[threadIdx.x - off] : 0;
        __syncthreads();
        s[threadIdx.x] += t;
        __syncthreads();
    }
    if (threadIdx.x < NB2) g_bsum[threadIdx.x] = s[threadIdx.x] - v;
}
__global__ void scan3_kernel() {
    int i = blockIdx.x * blockDim.x + threadIdx.x;
    if (i < KB) {
        g_off[i] += g_bsum[i >> 10];
        g_cur[i] = 0;
    }
    if (i == 0) g_off[KB] = EE;
}
__global__ void scatter_kernel(const int* __restrict__ ei, const int* __restrict__ et) {
    int e = blockIdx.x * blockDim.x + threadIdx.x;
    if (e >= EE) return;
    int key = ei[EE + e] * RR + et[e];
    int pos = g_off[key] + atomicAdd(&g_cur[key], 1);
    g_esrc[pos] = ei[e];
}
__global__ void build_lists_kernel() {
    int b = blockIdx.x * blockDim.x + threadIdx.x;
    if (b >= KB) return;
    if (g_deg[b] > 0) {
        int r = b & 7;
        int n = b >> 3;
        int idx = atomicAdd(&g_lcnt[r], 1);
        g_runidx[b] = r * NN + idx;
        g_lnode[r * NN + idx] = n;
    } else {
        g_runidx[b] = -1;
    }
}

// ---------------- kqv = h @ W_kqv + b (FFMA2 inner loop) ----------------
#define TILE_M 64
__global__ __launch_bounds__(256) void kqv_gemm_kernel(const float* __restrict__ W,
                                                       const float* __restrict__ bias) {
    extern __shared__ float sm[];
    float* Ws = sm;                   // 128*128 (one chunk)
    float* As = sm + 128 * 128;       // 64*129
    int tid = threadIdx.x;
    int row0 = blockIdx.x * TILE_M;

    for (int i = tid; i < TILE_M * 32; i += 256) {
        int row = i >> 5, c4 = i & 31;
        int gr = row0 + row;
        float4 v = (gr < NN) ? ((const float4*)(g_h + (size_t)gr * 128))[c4]
                             : make_float4(0.f, 0.f, 0.f, 0.f);
        float* d = As + row * 129 + c4 * 4;
        d[0] = v.x; d[1] = v.y; d[2] = v.z; d[3] = v.w;
    }

    int nl = tid & 63;
    int cg = tid >> 6;
    int grow = row0 + nl;
    const float4* W4 = (const float4*)W;
    float4* Ws4 = (float4*)Ws;

    for (int chunk = 0; chunk < 3; chunk++) {
        __syncthreads();
        for (int i = tid; i < 128 * 32; i += 256) {
            int k = i >> 5, c4 = i & 31;
            Ws4[k * 32 + c4] = W4[k * 96 + chunk * 32 + c4];
        }
        __syncthreads();

        int col0 = cg * 32;
        ull acc2[16];
#pragma unroll
        for (int c = 0; c < 16; c++) acc2[c] = 0ull;
        for (int k = 0; k < 128; k++) {
            ull aa = pack2(As[nl * 129 + k]);
            const ulonglong2* wrow = (const ulonglong2*)(Ws + k * 128 + col0);
#pragma unroll
            for (int j = 0; j < 8; j++) {
                ulonglong2 w = wrow[j];
                FMA2(acc2[2 * j], aa, w.x);
                FMA2(acc2[2 * j + 1], aa, w.y);
            }
        }
        if (grow < NN) {
            float* o = g_kqv + (size_t)grow * 384 + chunk * 128 + col0;
#pragma unroll
            for (int j = 0; j < 16; j++) {
                float2 v = unpack2(acc2[j]);
                o[2 * j]     = v.x + bias[chunk * 128 + col0 + 2 * j];
                o[2 * j + 1] = v.y + bias[chunk * 128 + col0 + 2 * j + 1];
            }
        }
    }
}

// ---------------- q~ = (pr*scale) * Wk[r] q[n] per nonempty run (FFMA2) ----------------
__global__ __launch_bounds__(256) void qt_kernel(const float* __restrict__ Wk,
                                                 const float* __restrict__ pr) {
    extern __shared__ float sm[];
    float* WkT = sm;            // 4096
    float* As = sm + 4096;      // 64*129
    int tid = threadIdx.x;
    int r = blockIdx.y;
    int cnt = g_lcnt[r];
    int e0 = blockIdx.x * 64;
    if (e0 >= cnt) return;

    const float* WkR = Wk + (size_t)r * 4096;   // [h][d][f]
    for (int i = tid; i < 4096; i += 256) {
        int h = i >> 10, rem = i & 1023, d = rem >> 5, f = rem & 31;
        WkT[h * 1024 + f * 32 + d] = WkR[i];
    }
    for (int i = tid; i < 64 * 32; i += 256) {
        int row = i >> 5, c4 = i & 31;
        int entry = e0 + row;
        float4 v = make_float4(0.f, 0.f, 0.f, 0.f);
        if (entry < cnt) {
            int n = g_lnode[r * NN + entry];
            v = ((const float4*)(g_kqv + (size_t)n * 384 + 128))[c4];
        }
        float* d = As + row * 129 + c4 * 4;
        d[0] = v.x; d[1] = v.y; d[2] = v.z; d[3] = v.w;
    }
    __syncthreads();

    int i = tid & 63, h = tid >> 6;
    int entry = e0 + i;
    ull acc2[16];
#pragma unroll
    for (int c = 0; c < 16; c++) acc2[c] = 0ull;
    const float* qrow = As + i * 129 + h * 32;
    for (int f = 0; f < 32; f++) {
        ull aa = pack2(qrow[f]);
        const ulonglong2* w2 = (const ulonglong2*)(WkT + h * 1024 + f * 32);
#pragma unroll
        for (int j = 0; j < 8; j++) {
            ulonglong2 w = w2[j];
            FMA2(acc2[2 * j], aa, w.x);
            FMA2(acc2[2 * j + 1], aa, w.y);
        }
    }
    if (entry < cnt) {
        float prscale = pr[r * 4 + h] * 0.17677669529663689f;   // pr * 1/sqrt(32)
        float* o = g_Qt + ((size_t)(r * NN + entry)) * 128 + h * 32;
#pragma unroll
        for (int j = 0; j < 16; j++) {
            float2 v = unpack2(acc2[j]);
            o[2 * j]     = v.x * prscale;
            o[2 * j + 1] = v.y * prscale;
        }
    }
}

// ---------------- attention: warp per dst node, per-run raw flash state ----------------
__global__ __launch_bounds__(256) void attn_kernel() {
    int n = (blockIdx.x * blockDim.x + threadIdx.x) >> 5;
    int lane = threadIdx.x & 31;
    if (n >= NN) return;
    const unsigned FULL = 0xffffffffu;

    int base = n * RR;
    for (int r = 0; r < RR; r++) {
        int beg = g_off[base + r];
        int end = g_off[base + r + 1];
        if (beg == end) continue;
        int ridx = g_runidx[base + r];
        const float* qt = g_Qt + (size_t)ridx * 128;
        float qt0 = qt[lane], qt1 = qt[32 + lane], qt2 = qt[64 + lane], qt3 = qt[96 + lane];

        float rm0 = -INFINITY, rm1 = -INFINITY, rm2 = -INFINITY, rm3 = -INFINITY;
        float rd0 = 0.f, rd1 = 0.f, rd2 = 0.f, rd3 = 0.f;
        float ra0 = 0.f, ra1 = 0.f, ra2 = 0.f, ra3 = 0.f;

        for (int e = beg; e < end; e++) {
            int src = g_esrc[e];
            const float* kb = g_kqv + (size_t)src * 384;
            float k0 = kb[lane], k1 = kb[32 + lane], k2 = kb[64 + lane], k3 = kb[96 + lane];
            float v0 = kb[256 + lane], v1 = kb[288 + lane], v2 = kb[320 + lane], v3 = kb[352 + lane];
            float p0 = k0 * qt0, p1 = k1 * qt1, p2 = k2 * qt2, p3 = k3 * qt3;
#pragma unroll
            for (int off = 16; off > 0; off >>= 1) {
                p0 += __shfl_xor_sync(FULL, p0, off);
                p1 += __shfl_xor_sync(FULL, p1, off);
                p2 += __shfl_xor_sync(FULL, p2, off);
                p3 += __shfl_xor_sync(FULL, p3, off);
            }
            float nm, c, w;
            nm = fmaxf(rm0, p0); c = __expf(rm0 - nm); w = __expf(p0 - nm);
            rd0 = rd0 * c + w; ra0 = ra0 * c + w * v0; rm0 = nm;
            nm = fmaxf(rm1, p1); c = __expf(rm1 - nm); w = __expf(p1 - nm);
            rd1 = rd1 * c + w; ra1 = ra1 * c + w * v1; rm1 = nm;
            nm = fmaxf(rm2, p2); c = __expf(rm2 - nm); w = __expf(p2 - nm);
            rd2 = rd2 * c + w; ra2 = ra2 * c + w * v2; rm2 = nm;
            nm = fmaxf(rm3, p3); c = __expf(rm3 - nm); w = __expf(p3 - nm);
            rd3 = rd3 * c + w; ra3 = ra3 * c + w * v3; rm3 = nm;
        }

        if (lane == 0) {
            g_rm[(size_t)ridx * 4 + 0] = rm0; g_rm[(size_t)ridx * 4 + 1] = rm1;
            g_rm[(size_t)ridx * 4 + 2] = rm2; g_rm[(size_t)ridx * 4 + 3] = rm3;
            g_rd[(size_t)ridx * 4 + 0] = rd0; g_rd[(size_t)ridx * 4 + 1] = rd1;
            g_rd[(size_t)ridx * 4 + 2] = rd2; g_rd[(size_t)ridx * 4 + 3] = rd3;
        }
        float* vr = g_Vr + (size_t)ridx * 128;
        vr[lane] = ra0; vr[32 + lane] = ra1; vr[64 + lane] = ra2; vr[96 + lane] = ra3;
    }
}

// ---------------- apply Wv[r] to raw per-run v-sums in place (FFMA2) ----------------
__global__ __launch_bounds__(256) void vt_kernel(const float* __restrict__ Wv) {
    extern __shared__ float sm[];
    float* WvS = sm;            // 4096 : [h][d][f]
    float* As = sm + 4096;      // 64*129
    int tid = threadIdx.x;
    int r = blockIdx.y;
    int cnt = g_lcnt[r];
    int e0 = blockIdx.x * 64;
    if (e0 >= cnt) return;

    const float* WvR = Wv + (size_t)r * 4096;
    for (int i = tid; i < 4096; i += 256) WvS[i] = WvR[i];
    for (int i = tid; i < 64 * 32; i += 256) {
        int row = i >> 5, c4 = i & 31;
        int entry = e0 + row;
        float4 v = make_float4(0.f, 0.f, 0.f, 0.f);
        if (entry < cnt)
            v = ((const float4*)(g_Vr + ((size_t)(r * NN + entry)) * 128))[c4];
        float* d = As + row * 129 + c4 * 4;
        d[0] = v.x; d[1] = v.y; d[2] = v.z; d[3] = v.w;
    }
    __syncthreads();

    int i = tid & 63, h = tid >> 6;
    int entry = e0 + i;
    ull acc2[16];
#pragma unroll
    for (int c = 0; c < 16; c++) acc2[c] = 0ull;
    const float* arow = As + i * 129 + h * 32;
    for (int d = 0; d < 32; d++) {
        ull aa = pack2(arow[d]);
        const ulonglong2* w2 = (const ulonglong2*)(WvS + h * 1024 + d * 32);
#pragma unroll
        for (int j = 0; j < 8; j++) {
            ulonglong2 w = w2[j];
            FMA2(acc2[2 * j], aa, w.x);
            FMA2(acc2[2 * j + 1], aa, w.y);
        }
    }
    if (entry < cnt) {
        float* o = g_Vr + ((size_t)(r * NN + entry)) * 128 + h * 32;
#pragma unroll
        for (int j = 0; j < 16; j++) {
            float2 v = unpack2(acc2[j]);
            o[2 * j] = v.x;
            o[2 * j + 1] = v.y;
        }
    }
}

// ---------------- merge runs per node, finalize softmax ----------------
__global__ __launch_bounds__(256) void merge_kernel() {
    int n = (blockIdx.x * blockDim.x + threadIdx.x) >> 5;
    int lane = threadIdx.x & 31;
    if (n >= NN) return;

    float M0 = -INFINITY, M1 = -INFINITY, M2 = -INFINITY, M3 = -INFINITY;
    float D0 = 0.f, D1 = 0.f, D2 = 0.f, D3 = 0.f;
    float O0 = 0.f, O1 = 0.f, O2 = 0.f, O3 = 0.f;

    int base = n * RR;
    for (int r = 0; r < RR; r++) {
        int ridx = g_runidx[base + r];
        if (ridx < 0) continue;
        float m0 = g_rm[(size_t)ridx * 4 + 0], m1 = g_rm[(size_t)ridx * 4 + 1];
        float m2 = g_rm[(size_t)ridx * 4 + 2], m3 = g_rm[(size_t)ridx * 4 + 3];
        float d0 = g_rd[(size_t)ridx * 4 + 0], d1 = g_rd[(size_t)ridx * 4 + 1];
        float d2 = g_rd[(size_t)ridx * 4 + 2], d3 = g_rd[(size_t)ridx * 4 + 3];
        const float* vr = g_Vr + (size_t)ridx * 128;
        float v0 = vr[lane], v1 = vr[32 + lane], v2 = vr[64 + lane], v3 = vr[96 + lane];

        float nm, c1, c2;
        nm = fmaxf(M0, m0); c1 = __expf(M0 - nm); c2 = __expf(m0 - nm);
        D0 = D0 * c1 + d0 * c2; O0 = O0 * c1 + v0 * c2; M0 = nm;
        nm = fmaxf(M1, m1); c1 = __expf(M1 - nm); c2 = __expf(m1 - nm);
        D1 = D1 * c1 + d1 * c2; O1 = O1 * c1 + v1 * c2; M1 = nm;
        nm = fmaxf(M2, m2); c1 = __expf(M2 - nm); c2 = __expf(m2 - nm);
        D2 = D2 * c1 + d2 * c2; O2 = O2 * c1 + v2 * c2; M2 = nm;
        nm = fmaxf(M3, m3); c1 = __expf(M3 - nm); c2 = __expf(m3 - nm);
        D3 = D3 * c1 + d3 * c2; O3 = O3 * c1 + v3 * c2; M3 = nm;
    }
    float* og = g_aggr + (size_t)n * 128;
    og[lane]      = (D0 > 0.f) ? O0 / D0 : 0.f;
    og[32 + lane] = (D1 > 0.f) ? O1 / D1 : 0.f;
    og[64 + lane] = (D2 > 0.f) ? O2 / D2 : 0.f;
    og[96 + lane] = (D3 > 0.f) ? O3 / D3 : 0.f;
}

// ---------------- out: o = gelu(aggr) @ W_out + b; h = relu(sg*o + (1-sg)*h) ----------------
__global__ __launch_bounds__(256) void out_gemm_kernel(const float* __restrict__ W,
                                                       const float* __restrict__ bias,
                                                       const float* __restrict__ skip,
                                                       int l, float* __restrict__ out2) {
    extern __shared__ float sm[];
    float* Ws = sm;                // 128*128
    float* As = sm + 128 * 128;    // 64*129
    int tid = threadIdx.x;
    int row0 = blockIdx.x * TILE_M;

    const float4* W4 = (const float4*)W;
    float4* Ws4 = (float4*)Ws;
    for (int i = tid; i < 128 * 128 / 4; i += 256) Ws4[i] = W4[i];
    for (int i = tid; i < TILE_M * 32; i += 256) {
        int row = i >> 5, c4 = i & 31;
        int gr = row0 + row;
        float4 v = (gr < NN) ? ((const float4*)(g_aggr + (size_t)gr * 128))[c4]
                             : make_float4(0.f, 0.f, 0.f, 0.f);
        float* d = As + row * 129 + c4 * 4;
        d[0] = 0.5f * v.x * (1.f + erff(v.x * 0.70710678118654752f));
        d[1] = 0.5f * v.y * (1.f + erff(v.y * 0.70710678118654752f));
        d[2] = 0.5f * v.z * (1.f + erff(v.z * 0.70710678118654752f));
        d[3] = 0.5f * v.w * (1.f + erff(v.w * 0.70710678118654752f));
    }
    __syncthreads();

    int nl = tid & 63;
    int cg = tid >> 6;
    int grow = row0 + nl;
    int col0 = cg * 32;
    ull acc2[16];
#pragma unroll
    for (int c = 0; c < 16; c++) acc2[c] = 0ull;
    for (int k = 0; k < 128; k++) {
        ull aa = pack2(As[nl * 129 + k]);
        const ulonglong2* wrow = (const ulonglong2*)(Ws + k * 128 + col0);
#pragma unroll
        for (int j = 0; j < 8; j++) {
            ulonglong2 w = wrow[j];
            FMA2(acc2[2 * j], aa, w.x);
            FMA2(acc2[2 * j + 1], aa, w.y);
        }
    }
    if (grow < NN) {
        float sg = 1.f / (1.f + expf(-skip[l]));
        float* hrow = g_h + (size_t)grow * 128 + col0;
#pragma unroll
        for (int j = 0; j < 16; j++) {
            float2 v = unpack2(acc2[j]);
            float oA = v.x + bias[col0 + 2 * j];
            float oB = v.y + bias[col0 + 2 * j + 1];
            float hA = fmaxf(sg * oA + (1.f - sg) * hrow[2 * j], 0.f);
            float hB = fmaxf(sg * oB + (1.f - sg) * hrow[2 * j + 1], 0.f);
            hrow[2 * j] = hA;
            hrow[2 * j + 1] = hB;
            if (out2) {
                out2[(size_t)grow * 128 + col0 + 2 * j] = hA;
                out2[(size_t)grow * 128 + col0 + 2 * j + 1] = hB;
            }
        }
    }
}

// ---------------- host ----------------
extern "C" void kernel_launch(void* const* d_in, const int* in_sizes, int n_in,
                              void* d_out, int out_size) {
    const float* emb   = (const float*)d_in[0];
    const float* W_kqv = (const float*)d_in[1];
    const float* b_kqv = (const float*)d_in[2];
    const float* Wk    = (const float*)d_in[3];
    const float* Wv    = (const float*)d_in[4];
    const float* p_rel = (const float*)d_in[5];
    const float* W_out = (const float*)d_in[6];
    const float* b_out = (const float*)d_in[7];
    const float* skip  = (const float*)d_in[8];
    const int*   x     = (const int*)d_in[9];
    const int*   ei    = (const int*)d_in[10];
    const int*   et    = (const int*)d_in[11];
    float* out = (float*)d_out;

    const int SMEM_GEMM = (128 * 128 + 64 * 129) * 4;    // 98560
    const int SMEM_QT   = (4096 + 64 * 129) * 4;         // 49408
    static bool attr_set = false;
    if (!attr_set) {
        cudaFuncSetAttribute(kqv_gemm_kernel, cudaFuncAttributeMaxDynamicSharedMemorySize, SMEM_GEMM);
        cudaFuncSetAttribute(out_gemm_kernel, cudaFuncAttributeMaxDynamicSharedMemorySize, SMEM_GEMM);
        cudaFuncSetAttribute(qt_kernel, cudaFuncAttributeMaxDynamicSharedMemorySize, SMEM_QT);
        cudaFuncSetAttribute(vt_kernel, cudaFuncAttributeMaxDynamicSharedMemorySize, SMEM_QT);
        attr_set = true;
    }

    const int nblocks_nh = (NN * HID + 255) / 256;
    const int nblocks_m  = (NN + TILE_M - 1) / TILE_M;   // 1563
    const int nblocks_e  = (EE + 255) / 256;
    const int nblocks_kb = (KB + 255) / 256;
    const int nblocks_kb1 = (KB + 1 + 255) / 256;
    const int nblocks_w  = (NN * 32 + 255) / 256;        // warp per node: 12500

    gather_kernel<<<nblocks_nh, 256>>>(emb, x);

    // sort edges by (dst, rel) into CSR + compact run lists
    zero_deg_kernel<<<nblocks_kb, 256>>>();
    hist_kernel<<<nblocks_e, 256>>>(ei, et);
    scan1_kernel<<<NB2, 1024>>>();
    scan2_kernel<<<1, 1024>>>();
    scan3_kernel<<<nblocks_kb1, 256>>>();
    scatter_kernel<<<nblocks_e, 256>>>(ei, et);
    build_lists_kernel<<<nblocks_kb, 256>>>();

    dim3 tg(nblocks_m, RR);
    for (int l = 0; l < LL; l++) {
        const float* Wkqv_l = W_kqv + (size_t)l * HID * 3 * HID;
        const float* bkqv_l = b_kqv + (size_t)l * 3 * HID;
        const float* Wk_l   = Wk + (size_t)l * RR * HH * DD * DD;
        const float* Wv_l   = Wv + (size_t)l * RR * HH * DD * DD;
        const float* pr_l   = p_rel + (size_t)l * RR * HH;
        const float* Wout_l = W_out + (size_t)l * HID * HID;
        const float* bout_l = b_out + (size_t)l * HID;

        kqv_gemm_kernel<<<nblocks_m, 256, SMEM_GEMM>>>(Wkqv_l, bkqv_l);
        qt_kernel<<<tg, 256, SMEM_QT>>>(Wk_l, pr_l);
        attn_kernel<<<nblocks_w, 256>>>();
        vt_kernel<<<tg, 256, SMEM_QT>>>(Wv_l);
        merge_kernel<<<nblocks_w, 256>>>();
        out_gemm_kernel<<<nblocks_m, 256, SMEM_GEMM>>>(Wout_l, bout_l, skip, l,
                                                       (l == LL - 1) ? out : nullptr);
    }
}